// round 15
// baseline (speedup 1.0000x reference)
#include <cuda_runtime.h>
#include <cuda_bf16.h>
#include <cstdint>
#include <math.h>

// ---------------------------------------------------------------------------
// Problem constants
// ---------------------------------------------------------------------------
#define NROWS 8192
#define DIM   256
constexpr float INV_TEMP = 1.0f / 0.07f;
constexpr float ALPHA = 1.44269504088896341f / 0.07f;  // log2(e)/T, folded into X

// Banding at occupancy 2: each 128-thread CTA owns a 128-column B panel;
// A streams in 32-row strips. Two CTAs per SM cover each other's stalls.
#define THREADS 128
#define GRIDSZ  304                      // 2 persistent CTAs per SM
#define BANDC   128                      // y rows per band
#define SROWS   32                       // x rows per strip
#define SPB     256                      // strips per band (8192/32)
#define TSTRIPS 16384                    // 64 bands * 256 strips

// SMEM: B panel 64KB resident + A double buffer 2x16KB = 96KB (2 CTAs -> 192KB)
#define ROWB   512                       // bytes per smem row (256 bf16)
#define SM_B   0
#define SM_A(p) (BANDC * ROWB + (p) * (SROWS * ROWB))
#define SMEM_TOTAL (BANDC * ROWB + 2 * SROWS * ROWB)   // 98304

// ---------------------------------------------------------------------------
// Scratch (device globals; no allocations allowed)
// ---------------------------------------------------------------------------
__device__ float g_rowsum[NROWS];
__device__ float g_diag[NROWS];
__device__ unsigned int g_ctr;
__device__ float* g_outp;
__device__ __nv_bfloat16 g_xb[NROWS * DIM];   // x * ALPHA, bf16
__device__ __nv_bfloat16 g_yb[NROWS * DIM];   // y, bf16

// ---------------------------------------------------------------------------
// Helpers
// ---------------------------------------------------------------------------
__device__ __forceinline__ uint32_t smem_to_u32(const void* p) {
    uint32_t a;
    asm("{ .reg .u64 t; cvta.to.shared.u64 t, %1; cvt.u32.u64 %0, t; }"
        : "=r"(a) : "l"(p));
    return a;
}
__device__ __forceinline__ void cp16(uint32_t saddr, const void* gaddr) {
    asm volatile("cp.async.cg.shared.global [%0], [%1], 16;"
                 :: "r"(saddr), "l"(gaddr) : "memory");
}
#define CP_COMMIT()  asm volatile("cp.async.commit_group;" ::: "memory")
#define CP_WAIT0()   asm volatile("cp.async.wait_group 0;" ::: "memory")

#define LDSM4(r0, r1, r2, r3, addr)                                          \
    asm volatile("ldmatrix.sync.aligned.m8n8.x4.shared.b16 {%0,%1,%2,%3}, [%4];" \
                 : "=r"(r0), "=r"(r1), "=r"(r2), "=r"(r3) : "r"(addr))

#define MMA16816(d, a, b0, b1)                                               \
    asm volatile("mma.sync.aligned.m16n8k16.row.col.f32.bf16.bf16.f32 "      \
                 "{%0,%1,%2,%3}, {%4,%5,%6,%7}, {%8,%9}, {%0,%1,%2,%3};"     \
                 : "+f"(d[0]), "+f"(d[1]), "+f"(d[2]), "+f"(d[3])            \
                 : "r"(a[0]), "r"(a[1]), "r"(a[2]), "r"(a[3]),               \
                   "r"(b0), "r"(b1))

__device__ __forceinline__ float ex2f(float x) {
    float v;
    asm("ex2.approx.ftz.f32 %0, %1;" : "=f"(v) : "f"(x));
    return v;
}
__device__ __forceinline__ float lg2f(float x) {
    float v;
    asm("lg2.approx.ftz.f32 %0, %1;" : "=f"(v) : "f"(x));
    return v;
}

// Swizzled smem address: row stride 512B, XOR low-3 16B-chunk bits with row&7
#define SWA(base, r, c) ((base) + (r) * ROWB + ((((c) ^ ((r) & 7))) << 4))

// ---------------------------------------------------------------------------
// Kernel: fused prep — convert X*ALPHA and Y to bf16, diag dots, zero rowsum,
// zero completion counter, stash the output pointer.
// ---------------------------------------------------------------------------
__global__ __launch_bounds__(256) void prep_kernel(const float* __restrict__ X,
                                                   const float* __restrict__ Y,
                                                   float* out) {
    const int warp = threadIdx.x >> 5, lane = threadIdx.x & 31;
    const int r = blockIdx.x * 8 + warp;
    const float4* X4 = reinterpret_cast<const float4*>(X) + (size_t)r * (DIM / 4);
    const float4* Y4 = reinterpret_cast<const float4*>(Y) + (size_t)r * (DIM / 4);
    float s = 0.0f;
    #pragma unroll
    for (int i = 0; i < 2; i++) {
        int idx = lane + 32 * i;
        float4 a = X4[idx];
        float4 b = Y4[idx];
        s += a.x * b.x + a.y * b.y + a.z * b.z + a.w * b.w;
        __nv_bfloat162 ax = __floats2bfloat162_rn(a.x * ALPHA, a.y * ALPHA);
        __nv_bfloat162 ay = __floats2bfloat162_rn(a.z * ALPHA, a.w * ALPHA);
        __nv_bfloat162 bx = __floats2bfloat162_rn(b.x, b.y);
        __nv_bfloat162 by = __floats2bfloat162_rn(b.z, b.w);
        uint2 ua, ub;
        ua.x = *reinterpret_cast<uint32_t*>(&ax);
        ua.y = *reinterpret_cast<uint32_t*>(&ay);
        ub.x = *reinterpret_cast<uint32_t*>(&bx);
        ub.y = *reinterpret_cast<uint32_t*>(&by);
        *reinterpret_cast<uint2*>(g_xb + (size_t)r * DIM + idx * 4) = ua;
        *reinterpret_cast<uint2*>(g_yb + (size_t)r * DIM + idx * 4) = ub;
    }
    #pragma unroll
    for (int o = 16; o > 0; o >>= 1) s += __shfl_xor_sync(0xFFFFFFFFu, s, o);
    if (lane == 0) {
        g_diag[r] = s;
        g_rowsum[r] = 0.0f;
    }
    if (blockIdx.x == 0 && threadIdx.x == 0) {
        g_ctr = 0u;
        g_outp = out;
    }
}

// ---------------------------------------------------------------------------
// GEMM: banded occ=2 kernel (round-14 structure) + fused last-CTA loss tail.
// Register pressure ~130 here, far from the 254 cliff that killed the occ=1
// fusion attempts, so the tail cannot induce in-loop spills.
// ---------------------------------------------------------------------------
__device__ __forceinline__ void load_B_panel(uint32_t Bb, int band, int tid) {
    const __nv_bfloat16* Bg = g_yb + (size_t)band * BANDC * DIM;
    #pragma unroll
    for (int it = 0; it < 32; it++) {
        int idx = tid + it * THREADS;      // 0..4095
        int r = idx >> 5, c = idx & 31;
        cp16(SWA(Bb, r, c), Bg + (size_t)r * DIM + c * 8);
    }
}
__device__ __forceinline__ void load_A_strip(uint32_t Ab, int srow, int tid) {
    const __nv_bfloat16* Ag = g_xb + (size_t)srow * SROWS * DIM;
    #pragma unroll
    for (int it = 0; it < 8; it++) {
        int idx = tid + it * THREADS;      // 0..1023
        int r = idx >> 5, c = idx & 31;
        cp16(SWA(Ab, r, c), Ag + (size_t)r * DIM + c * 8);
    }
}

// Compute strip into aN while doing the exp-epilogue of aO (rows row_old..+31).
__device__ __forceinline__ void strip_compute(
    uint32_t Ab, uint32_t Bb, int n_base,
    int a_row_off, int a_c_off, int b_row_off, int b_c_off,
    float (&aN)[2][4][4], float (&aO)[2][4][4],
    int row_old, int lid)
{
    #pragma unroll
    for (int i = 0; i < 2; i++)
        #pragma unroll
        for (int j = 0; j < 4; j++)
            #pragma unroll
            for (int r = 0; r < 4; r++) aN[i][j][r] = 0.0f;

    float lo[2] = {0.f, 0.f}, hi[2] = {0.f, 0.f};

    #pragma unroll
    for (int kk = 0; kk < 16; kk++) {
        uint32_t a[2][4];
        #pragma unroll
        for (int mi = 0; mi < 2; mi++) {
            int row = mi * 16 + a_row_off;
            int c = kk * 2 + a_c_off;
            LDSM4(a[mi][0], a[mi][1], a[mi][2], a[mi][3], SWA(Ab, row, c));
        }
        uint32_t b[2][4];
        #pragma unroll
        for (int p = 0; p < 2; p++) {
            int nrow = n_base + p * 16 + b_row_off;
            int c = kk * 2 + b_c_off;
            LDSM4(b[p][0], b[p][1], b[p][2], b[p][3], SWA(Bb, nrow, c));
        }
        // Interleave 2 elements of the previous strip's exp-epilogue.
        #pragma unroll
        for (int j = 0; j < 2; j++) {
            int e = kk * 2 + j;                    // 0..31
            int mi = e >> 4, ni = (e >> 2) & 3, r = e & 3;
            float v = ex2f(aO[mi][ni][r]);
            if (r < 2) lo[mi] += v; else hi[mi] += v;
        }
        #pragma unroll
        for (int mi = 0; mi < 2; mi++)
            #pragma unroll
            for (int ni = 0; ni < 4; ni++)
                MMA16816(aN[mi][ni], a[mi],
                         b[ni >> 1][(ni & 1) << 1],
                         b[ni >> 1][((ni & 1) << 1) + 1]);
    }

    // Finish previous strip: quad-shuffle row reduce + atomics.
    const int g = lid >> 2;
    #pragma unroll
    for (int mi = 0; mi < 2; mi++) {
        float l = lo[mi], h = hi[mi];
        l += __shfl_xor_sync(0xFFFFFFFFu, l, 1);
        l += __shfl_xor_sync(0xFFFFFFFFu, l, 2);
        h += __shfl_xor_sync(0xFFFFFFFFu, h, 1);
        h += __shfl_xor_sync(0xFFFFFFFFu, h, 2);
        if ((lid & 3) == 0) {
            atomicAdd(&g_rowsum[row_old + mi * 16 + g], l);
            atomicAdd(&g_rowsum[row_old + mi * 16 + g + 8], h);
        }
    }
}

// Epilogue-only flush for the final strip.
__device__ __forceinline__ void flush_acc(float (&aO)[2][4][4], int row_old, int lid) {
    const int g = lid >> 2;
    #pragma unroll
    for (int mi = 0; mi < 2; mi++) {
        float l = 0.f, h = 0.f;
        #pragma unroll
        for (int ni = 0; ni < 4; ni++) {
            l += ex2f(aO[mi][ni][0]) + ex2f(aO[mi][ni][1]);
            h += ex2f(aO[mi][ni][2]) + ex2f(aO[mi][ni][3]);
        }
        l += __shfl_xor_sync(0xFFFFFFFFu, l, 1);
        l += __shfl_xor_sync(0xFFFFFFFFu, l, 2);
        h += __shfl_xor_sync(0xFFFFFFFFu, h, 1);
        h += __shfl_xor_sync(0xFFFFFFFFu, h, 2);
        if ((lid & 3) == 0) {
            atomicAdd(&g_rowsum[row_old + mi * 16 + g], l);
            atomicAdd(&g_rowsum[row_old + mi * 16 + g + 8], h);
        }
    }
}

__global__ __launch_bounds__(THREADS, 2) void simsum_hmma_kernel() {
    extern __shared__ char smem[];
    const uint32_t sb = smem_to_u32(smem);
    const int tid = threadIdx.x;
    const int wid = tid >> 5, lid = tid & 31;
    const int n_base = wid * 32;               // warp grid 1 (M) x 4 (N)

    const int sub = lid >> 3, l7 = lid & 7;
    const int a_row_off = ((sub & 1) << 3) + l7;
    const int a_c_off   = sub >> 1;
    const int b_row_off = ((sub >> 1) << 3) + l7;
    const int b_c_off   = sub & 1;

    const int start = (int)(((long)blockIdx.x * TSTRIPS) / GRIDSZ);
    const int end   = (int)(((long)(blockIdx.x + 1) * TSTRIPS) / GRIDSZ);

    // Ping-pong accumulators; init so the first (fake) epilogue adds 0.
    float accA[2][4][4], accB[2][4][4];
    #pragma unroll
    for (int i = 0; i < 2; i++)
        #pragma unroll
        for (int j = 0; j < 4; j++)
            #pragma unroll
            for (int r = 0; r < 4; r++) { accA[i][j][r] = -1e30f; accB[i][j][r] = -1e30f; }

    int row_old = 0;
    int pcur = 0;
    for (int w = start; w < end; w++) {
        const int band = w >> 8, srow = w & (SPB - 1);
        if (srow == 0 || w == start) {
            CP_WAIT0();
            __syncthreads();                   // all warps done with old B panel
            load_B_panel(sb + SM_B, band, tid);
            load_A_strip(sb + SM_A(0), srow, tid);
            CP_COMMIT();
            CP_WAIT0();
            __syncthreads();
            pcur = 0;
        } else {
            CP_WAIT0();                        // prefetched A strip landed
            __syncthreads();
        }
        const bool pf = (w + 1 < end) && (((w + 1) & (SPB - 1)) != 0);
        if (pf) {
            load_A_strip(sb + SM_A(pcur ^ 1), srow + 1, tid);
            CP_COMMIT();
        }

        if ((w - start) & 1)
            strip_compute(sb + SM_A(pcur), sb + SM_B, n_base,
                          a_row_off, a_c_off, b_row_off, b_c_off,
                          accB, accA, row_old, lid);
        else
            strip_compute(sb + SM_A(pcur), sb + SM_B, n_base,
                          a_row_off, a_c_off, b_row_off, b_c_off,
                          accA, accB, row_old, lid);

        row_old = srow * SROWS;
        if (pf) pcur ^= 1;
    }

    if ((end - start) & 1) flush_acc(accA, row_old, lid);
    else                   flush_acc(accB, row_old, lid);

    // ---- Fused loss tail: last of 304 CTAs computes the scalar loss. ----
    __threadfence();                 // make this CTA's REDs globally visible
    __syncthreads();                 // whole CTA has fenced
    unsigned int* ctr_slot = reinterpret_cast<unsigned int*>(smem + 4096);
    if (tid == 0) *ctr_slot = atomicAdd(&g_ctr, 1u);
    __syncthreads();
    if (*ctr_slot != GRIDSZ - 1) return;
    __threadfence();                 // acquire: order reads after counter win

    float* outp = g_outp;            // loaded post-fence; no span over the loop
    float* sh = reinterpret_cast<float*>(smem);
    float part = 0.0f;
    #pragma unroll 1
    for (int i = tid; i < NROWS; i += THREADS) {
        float d = g_diag[i] * INV_TEMP;
        float lneg = __ldcg(&g_rowsum[i]) - ex2f(d * 1.44269504f);
        part += lg2f(lneg) * 0.69314718056f - d;
    }
    sh[tid] = part;
    __syncthreads();
    #pragma unroll 1
    for (int o = 64; o > 0; o >>= 1) {
        if (tid < o) sh[tid] += sh[tid + o];
        __syncthreads();
    }
    if (tid == 0) outp[0] = sh[0] * (1.0f / NROWS);
}

// ---------------------------------------------------------------------------
// Entry point
// ---------------------------------------------------------------------------
extern "C" void kernel_launch(void* const* d_in, const int* in_sizes, int n_in,
                              void* d_out, int out_size) {
    const float* X = (const float*)d_in[0];
    const float* Y = (const float*)d_in[1];
    float* out = (float*)d_out;

    static bool attr_set = false;
    if (!attr_set) {
        cudaFuncSetAttribute(simsum_hmma_kernel,
                             cudaFuncAttributeMaxDynamicSharedMemorySize, SMEM_TOTAL);
        attr_set = true;
    }

    prep_kernel<<<NROWS / 8, 256>>>(X, Y, out);
    simsum_hmma_kernel<<<GRIDSZ, THREADS, SMEM_TOTAL>>>();
}

// round 16
// speedup vs baseline: 1.4254x; 1.4254x over previous
#include <cuda_runtime.h>
#include <cuda_bf16.h>
#include <cstdint>
#include <math.h>

// ---------------------------------------------------------------------------
// Problem constants
// ---------------------------------------------------------------------------
#define NROWS 8192
#define DIM   256
constexpr float INV_TEMP = 1.0f / 0.07f;
constexpr float ALPHA = 1.44269504088896341f / 0.07f;  // log2(e)/T, folded into X

// Banding at occupancy 2: each 128-thread CTA owns a 128-column B panel;
// A streams in 32-row strips. Two CTAs per SM cover each other's stalls.
#define THREADS 128
#define GRIDSZ  304                      // 2 persistent CTAs per SM
#define BANDC   128                      // y rows per band
#define SROWS   32                       // x rows per strip
#define SPB     256                      // strips per band (8192/32)
#define NBANDS  64                       // 8192/128
#define TSTRIPS 16384                    // NBANDS * SPB

// SMEM: B panel 64KB resident + A double buffer 2x16KB = 96KB (2 CTAs -> 192KB)
#define ROWB   512                       // bytes per smem row (256 bf16)
#define SM_B   0
#define SM_A(p) (BANDC * ROWB + (p) * (SROWS * ROWB))
#define SMEM_TOTAL (BANDC * ROWB + 2 * SROWS * ROWB)   // 98304

// ---------------------------------------------------------------------------
// Scratch (device globals; no allocations allowed)
// ---------------------------------------------------------------------------
__device__ float g_rowsum[NROWS];
__device__ float g_diag[NROWS];
__device__ __nv_bfloat16 g_xb[NROWS * DIM];   // x * ALPHA, bf16
__device__ __nv_bfloat16 g_yb[NROWS * DIM];   // y, bf16

// ---------------------------------------------------------------------------
// Helpers
// ---------------------------------------------------------------------------
__device__ __forceinline__ uint32_t smem_to_u32(const void* p) {
    uint32_t a;
    asm("{ .reg .u64 t; cvta.to.shared.u64 t, %1; cvt.u32.u64 %0, t; }"
        : "=r"(a) : "l"(p));
    return a;
}
__device__ __forceinline__ void cp16(uint32_t saddr, const void* gaddr) {
    asm volatile("cp.async.cg.shared.global [%0], [%1], 16;"
                 :: "r"(saddr), "l"(gaddr) : "memory");
}
#define CP_COMMIT()  asm volatile("cp.async.commit_group;" ::: "memory")
#define CP_WAIT0()   asm volatile("cp.async.wait_group 0;" ::: "memory")

#define LDSM4(r0, r1, r2, r3, addr)                                          \
    asm volatile("ldmatrix.sync.aligned.m8n8.x4.shared.b16 {%0,%1,%2,%3}, [%4];" \
                 : "=r"(r0), "=r"(r1), "=r"(r2), "=r"(r3) : "r"(addr))

#define MMA16816(d, a, b0, b1)                                               \
    asm volatile("mma.sync.aligned.m16n8k16.row.col.f32.bf16.bf16.f32 "      \
                 "{%0,%1,%2,%3}, {%4,%5,%6,%7}, {%8,%9}, {%0,%1,%2,%3};"     \
                 : "+f"(d[0]), "+f"(d[1]), "+f"(d[2]), "+f"(d[3])            \
                 : "r"(a[0]), "r"(a[1]), "r"(a[2]), "r"(a[3]),               \
                   "r"(b0), "r"(b1))

__device__ __forceinline__ float ex2f(float x) {
    float v;
    asm("ex2.approx.ftz.f32 %0, %1;" : "=f"(v) : "f"(x));
    return v;
}

// Swizzled smem address: row stride 512B, XOR low-3 16B-chunk bits with row&7
#define SWA(base, r, c) ((base) + (r) * ROWB + ((((c) ^ ((r) & 7))) << 4))

// ---------------------------------------------------------------------------
// Kernel: fused prep — convert X*ALPHA and Y to bf16, diag dots, zero rowsum.
// ---------------------------------------------------------------------------
__global__ __launch_bounds__(256) void prep_kernel(const float* __restrict__ X,
                                                   const float* __restrict__ Y,
                                                   float* __restrict__ out) {
    const int warp = threadIdx.x >> 5, lane = threadIdx.x & 31;
    const int r = blockIdx.x * 8 + warp;
    const float4* X4 = reinterpret_cast<const float4*>(X) + (size_t)r * (DIM / 4);
    const float4* Y4 = reinterpret_cast<const float4*>(Y) + (size_t)r * (DIM / 4);
    float s = 0.0f;
    #pragma unroll
    for (int i = 0; i < 2; i++) {
        int idx = lane + 32 * i;
        float4 a = X4[idx];
        float4 b = Y4[idx];
        s += a.x * b.x + a.y * b.y + a.z * b.z + a.w * b.w;
        __nv_bfloat162 ax = __floats2bfloat162_rn(a.x * ALPHA, a.y * ALPHA);
        __nv_bfloat162 ay = __floats2bfloat162_rn(a.z * ALPHA, a.w * ALPHA);
        __nv_bfloat162 bx = __floats2bfloat162_rn(b.x, b.y);
        __nv_bfloat162 by = __floats2bfloat162_rn(b.z, b.w);
        uint2 ua, ub;
        ua.x = *reinterpret_cast<uint32_t*>(&ax);
        ua.y = *reinterpret_cast<uint32_t*>(&ay);
        ub.x = *reinterpret_cast<uint32_t*>(&bx);
        ub.y = *reinterpret_cast<uint32_t*>(&by);
        *reinterpret_cast<uint2*>(g_xb + (size_t)r * DIM + idx * 4) = ua;
        *reinterpret_cast<uint2*>(g_yb + (size_t)r * DIM + idx * 4) = ub;
    }
    #pragma unroll
    for (int o = 16; o > 0; o >>= 1) s += __shfl_xor_sync(0xFFFFFFFFu, s, o);
    if (lane == 0) {
        g_diag[r] = s;
        g_rowsum[r] = 0.0f;
    }
    if (blockIdx.x == 0 && threadIdx.x == 0) out[0] = 0.0f;
}

// ---------------------------------------------------------------------------
// GEMM: banded occ=2 kernel. 128 threads (4 warps of 32 N-cols each);
// strip = 32 x-rows; exp-epilogue interleaved into the k-loop.
// DO NOT add code to this kernel — every fusion/addition attempt (R11, R12,
// R15) inflated the register allocation and regressed 20-40%.
// ---------------------------------------------------------------------------
__device__ __forceinline__ void load_B_panel(uint32_t Bb, int band, int tid) {
    const __nv_bfloat16* Bg = g_yb + (size_t)band * BANDC * DIM;
    #pragma unroll
    for (int it = 0; it < 32; it++) {
        int idx = tid + it * THREADS;      // 0..4095
        int r = idx >> 5, c = idx & 31;
        cp16(SWA(Bb, r, c), Bg + (size_t)r * DIM + c * 8);
    }
}
__device__ __forceinline__ void load_A_strip(uint32_t Ab, int srow, int tid) {
    const __nv_bfloat16* Ag = g_xb + (size_t)srow * SROWS * DIM;
    #pragma unroll
    for (int it = 0; it < 8; it++) {
        int idx = tid + it * THREADS;      // 0..1023
        int r = idx >> 5, c = idx & 31;
        cp16(SWA(Ab, r, c), Ag + (size_t)r * DIM + c * 8);
    }
}

// Compute strip into aN while doing the exp-epilogue of aO (rows row_old..+31).
__device__ __forceinline__ void strip_compute(
    uint32_t Ab, uint32_t Bb, int n_base,
    int a_row_off, int a_c_off, int b_row_off, int b_c_off,
    float (&aN)[2][4][4], float (&aO)[2][4][4],
    int row_old, int lid)
{
    #pragma unroll
    for (int i = 0; i < 2; i++)
        #pragma unroll
        for (int j = 0; j < 4; j++)
            #pragma unroll
            for (int r = 0; r < 4; r++) aN[i][j][r] = 0.0f;

    float lo[2] = {0.f, 0.f}, hi[2] = {0.f, 0.f};

    #pragma unroll
    for (int kk = 0; kk < 16; kk++) {
        uint32_t a[2][4];
        #pragma unroll
        for (int mi = 0; mi < 2; mi++) {
            int row = mi * 16 + a_row_off;
            int c = kk * 2 + a_c_off;
            LDSM4(a[mi][0], a[mi][1], a[mi][2], a[mi][3], SWA(Ab, row, c));
        }
        uint32_t b[2][4];
        #pragma unroll
        for (int p = 0; p < 2; p++) {
            int nrow = n_base + p * 16 + b_row_off;
            int c = kk * 2 + b_c_off;
            LDSM4(b[p][0], b[p][1], b[p][2], b[p][3], SWA(Bb, nrow, c));
        }
        // Interleave 2 elements of the previous strip's exp-epilogue.
        #pragma unroll
        for (int j = 0; j < 2; j++) {
            int e = kk * 2 + j;                    // 0..31
            int mi = e >> 4, ni = (e >> 2) & 3, r = e & 3;
            float v = ex2f(aO[mi][ni][r]);
            if (r < 2) lo[mi] += v; else hi[mi] += v;
        }
        #pragma unroll
        for (int mi = 0; mi < 2; mi++)
            #pragma unroll
            for (int ni = 0; ni < 4; ni++)
                MMA16816(aN[mi][ni], a[mi],
                         b[ni >> 1][(ni & 1) << 1],
                         b[ni >> 1][((ni & 1) << 1) + 1]);
    }

    // Finish previous strip: quad-shuffle row reduce + atomics.
    const int g = lid >> 2;
    #pragma unroll
    for (int mi = 0; mi < 2; mi++) {
        float l = lo[mi], h = hi[mi];
        l += __shfl_xor_sync(0xFFFFFFFFu, l, 1);
        l += __shfl_xor_sync(0xFFFFFFFFu, l, 2);
        h += __shfl_xor_sync(0xFFFFFFFFu, h, 1);
        h += __shfl_xor_sync(0xFFFFFFFFu, h, 2);
        if ((lid & 3) == 0) {
            atomicAdd(&g_rowsum[row_old + mi * 16 + g], l);
            atomicAdd(&g_rowsum[row_old + mi * 16 + g + 8], h);
        }
    }
}

// Epilogue-only flush for the final strip.
__device__ __forceinline__ void flush_acc(float (&aO)[2][4][4], int row_old, int lid) {
    const int g = lid >> 2;
    #pragma unroll
    for (int mi = 0; mi < 2; mi++) {
        float l = 0.f, h = 0.f;
        #pragma unroll
        for (int ni = 0; ni < 4; ni++) {
            l += ex2f(aO[mi][ni][0]) + ex2f(aO[mi][ni][1]);
            h += ex2f(aO[mi][ni][2]) + ex2f(aO[mi][ni][3]);
        }
        l += __shfl_xor_sync(0xFFFFFFFFu, l, 1);
        l += __shfl_xor_sync(0xFFFFFFFFu, l, 2);
        h += __shfl_xor_sync(0xFFFFFFFFu, h, 1);
        h += __shfl_xor_sync(0xFFFFFFFFu, h, 2);
        if ((lid & 3) == 0) {
            atomicAdd(&g_rowsum[row_old + mi * 16 + g], l);
            atomicAdd(&g_rowsum[row_old + mi * 16 + g + 8], h);
        }
    }
}

__global__ __launch_bounds__(THREADS, 2) void simsum_hmma_kernel() {
    extern __shared__ char smem[];
    const uint32_t sb = smem_to_u32(smem);
    const int tid = threadIdx.x;
    const int wid = tid >> 5, lid = tid & 31;
    const int n_base = wid * 32;               // warp grid 1 (M) x 4 (N)

    const int sub = lid >> 3, l7 = lid & 7;
    const int a_row_off = ((sub & 1) << 3) + l7;
    const int a_c_off   = sub >> 1;
    const int b_row_off = ((sub >> 1) << 3) + l7;
    const int b_c_off   = sub & 1;

    const int start = (int)(((long)blockIdx.x * TSTRIPS) / GRIDSZ);
    const int end   = (int)(((long)(blockIdx.x + 1) * TSTRIPS) / GRIDSZ);

    // Ping-pong accumulators; init so the first (fake) epilogue adds 0.
    float accA[2][4][4], accB[2][4][4];
    #pragma unroll
    for (int i = 0; i < 2; i++)
        #pragma unroll
        for (int j = 0; j < 4; j++)
            #pragma unroll
            for (int r = 0; r < 4; r++) { accA[i][j][r] = -1e30f; accB[i][j][r] = -1e30f; }

    int row_old = 0;
    int pcur = 0;
    for (int w = start; w < end; w++) {
        const int band = w >> 8, srow = w & (SPB - 1);
        if (srow == 0 || w == start) {
            CP_WAIT0();
            __syncthreads();                   // all warps done with old B panel
            load_B_panel(sb + SM_B, band, tid);
            load_A_strip(sb + SM_A(0), srow, tid);
            CP_COMMIT();
            CP_WAIT0();
            __syncthreads();
            pcur = 0;
        } else {
            CP_WAIT0();                        // prefetched A strip landed
            __syncthreads();
        }
        const bool pf = (w + 1 < end) && (((w + 1) & (SPB - 1)) != 0);
        if (pf) {
            load_A_strip(sb + SM_A(pcur ^ 1), srow + 1, tid);
            CP_COMMIT();
        }

        if ((w - start) & 1)
            strip_compute(sb + SM_A(pcur), sb + SM_B, n_base,
                          a_row_off, a_c_off, b_row_off, b_c_off,
                          accB, accA, row_old, lid);
        else
            strip_compute(sb + SM_A(pcur), sb + SM_B, n_base,
                          a_row_off, a_c_off, b_row_off, b_c_off,
                          accA, accB, row_old, lid);

        row_old = srow * SROWS;
        if (pf) pcur ^= 1;
    }

    if ((end - start) & 1) flush_acc(accA, row_old, lid);
    else                   flush_acc(accB, row_old, lid);
}

// ---------------------------------------------------------------------------
// Kernel: final loss — one row per thread, 32 blocks, atomic accumulate.
// ---------------------------------------------------------------------------
__global__ __launch_bounds__(256) void loss_kernel(float* __restrict__ out) {
    __shared__ float sh[256];
    int i = blockIdx.x * 256 + threadIdx.x;
    float d = g_diag[i] * INV_TEMP;
    float lneg = g_rowsum[i] - __expf(d);
    sh[threadIdx.x] = logf(lneg) - d;
    __syncthreads();
    #pragma unroll
    for (int o = 128; o > 0; o >>= 1) {
        if (threadIdx.x < o) sh[threadIdx.x] += sh[threadIdx.x + o];
        __syncthreads();
    }
    if (threadIdx.x == 0) atomicAdd(out, sh[0] * (1.0f / NROWS));
}

// ---------------------------------------------------------------------------
// Entry point
// ---------------------------------------------------------------------------
extern "C" void kernel_launch(void* const* d_in, const int* in_sizes, int n_in,
                              void* d_out, int out_size) {
    const float* X = (const float*)d_in[0];
    const float* Y = (const float*)d_in[1];
    float* out = (float*)d_out;

    static bool attr_set = false;
    if (!attr_set) {
        cudaFuncSetAttribute(simsum_hmma_kernel,
                             cudaFuncAttributeMaxDynamicSharedMemorySize, SMEM_TOTAL);
        attr_set = true;
    }

    prep_kernel<<<NROWS / 8, 256>>>(X, Y, out);
    simsum_hmma_kernel<<<GRIDSZ, THREADS, SMEM_TOTAL>>>();
    loss_kernel<<<NROWS / 256, 256>>>(out);
}

// round 17
// speedup vs baseline: 1.4334x; 1.0057x over previous
#include <cuda_runtime.h>
#include <cuda_bf16.h>
#include <cstdint>
#include <math.h>

// ---------------------------------------------------------------------------
// Problem constants
// ---------------------------------------------------------------------------
#define NROWS 8192
#define DIM   256
constexpr float INV_TEMP = 1.0f / 0.07f;
constexpr float ALPHA = 1.44269504088896341f / 0.07f;  // log2(e)/T, folded into X

// Banding at occupancy 2: each 128-thread CTA owns a 128-column B panel;
// A streams in 32-row strips. Two CTAs per SM cover each other's stalls.
#define THREADS 128
#define GRIDSZ  304                      // 2 persistent CTAs per SM
#define BANDC   128                      // y rows per band
#define SROWS   32                       // x rows per strip
#define SPB     256                      // strips per band (8192/32)
#define NBANDS  64                       // 8192/128
#define TSTRIPS 16384                    // NBANDS * SPB

// SMEM: B panel 64KB resident + A double buffer 2x16KB = 96KB (2 CTAs -> 192KB)
#define ROWB   512                       // bytes per smem row (256 bf16)
#define SM_B   0
#define SM_A(p) (BANDC * ROWB + (p) * (SROWS * ROWB))
#define SMEM_TOTAL (BANDC * ROWB + 2 * SROWS * ROWB)   // 98304

// ---------------------------------------------------------------------------
// Scratch (device globals; no allocations allowed)
// ---------------------------------------------------------------------------
__device__ float g_rowsum[NROWS];
__device__ float g_diag[NROWS];
__device__ __nv_bfloat16 g_xb[NROWS * DIM];   // x * ALPHA, bf16
__device__ __nv_bfloat16 g_yb[NROWS * DIM];   // y, bf16

// ---------------------------------------------------------------------------
// Helpers
// ---------------------------------------------------------------------------
__device__ __forceinline__ uint32_t smem_to_u32(const void* p) {
    uint32_t a;
    asm("{ .reg .u64 t; cvta.to.shared.u64 t, %1; cvt.u32.u64 %0, t; }"
        : "=r"(a) : "l"(p));
    return a;
}
__device__ __forceinline__ void cp16(uint32_t saddr, const void* gaddr) {
    asm volatile("cp.async.cg.shared.global [%0], [%1], 16;"
                 :: "r"(saddr), "l"(gaddr) : "memory");
}
#define CP_COMMIT()  asm volatile("cp.async.commit_group;" ::: "memory")
#define CP_WAIT0()   asm volatile("cp.async.wait_group 0;" ::: "memory")

#define LDSM4(r0, r1, r2, r3, addr)                                          \
    asm volatile("ldmatrix.sync.aligned.m8n8.x4.shared.b16 {%0,%1,%2,%3}, [%4];" \
                 : "=r"(r0), "=r"(r1), "=r"(r2), "=r"(r3) : "r"(addr))

#define MMA16816(d, a, b0, b1)                                               \
    asm volatile("mma.sync.aligned.m16n8k16.row.col.f32.bf16.bf16.f32 "      \
                 "{%0,%1,%2,%3}, {%4,%5,%6,%7}, {%8,%9}, {%0,%1,%2,%3};"     \
                 : "+f"(d[0]), "+f"(d[1]), "+f"(d[2]), "+f"(d[3])            \
                 : "r"(a[0]), "r"(a[1]), "r"(a[2]), "r"(a[3]),               \
                   "r"(b0), "r"(b1))

__device__ __forceinline__ float ex2f(float x) {
    float v;
    asm("ex2.approx.ftz.f32 %0, %1;" : "=f"(v) : "f"(x));
    return v;
}

// Swizzled smem address: row stride 512B, XOR low-3 16B-chunk bits with row&7
#define SWA(base, r, c) ((base) + (r) * ROWB + ((((c) ^ ((r) & 7))) << 4))

// ---------------------------------------------------------------------------
// Kernel: fused prep — convert X*ALPHA and Y to bf16, diag dots, zero rowsum.
// ---------------------------------------------------------------------------
__global__ __launch_bounds__(256) void prep_kernel(const float* __restrict__ X,
                                                   const float* __restrict__ Y,
                                                   float* __restrict__ out) {
    const int warp = threadIdx.x >> 5, lane = threadIdx.x & 31;
    const int r = blockIdx.x * 8 + warp;
    const float4* X4 = reinterpret_cast<const float4*>(X) + (size_t)r * (DIM / 4);
    const float4* Y4 = reinterpret_cast<const float4*>(Y) + (size_t)r * (DIM / 4);
    float s = 0.0f;
    #pragma unroll
    for (int i = 0; i < 2; i++) {
        int idx = lane + 32 * i;
        float4 a = X4[idx];
        float4 b = Y4[idx];
        s += a.x * b.x + a.y * b.y + a.z * b.z + a.w * b.w;
        __nv_bfloat162 ax = __floats2bfloat162_rn(a.x * ALPHA, a.y * ALPHA);
        __nv_bfloat162 ay = __floats2bfloat162_rn(a.z * ALPHA, a.w * ALPHA);
        __nv_bfloat162 bx = __floats2bfloat162_rn(b.x, b.y);
        __nv_bfloat162 by = __floats2bfloat162_rn(b.z, b.w);
        uint2 ua, ub;
        ua.x = *reinterpret_cast<uint32_t*>(&ax);
        ua.y = *reinterpret_cast<uint32_t*>(&ay);
        ub.x = *reinterpret_cast<uint32_t*>(&bx);
        ub.y = *reinterpret_cast<uint32_t*>(&by);
        *reinterpret_cast<uint2*>(g_xb + (size_t)r * DIM + idx * 4) = ua;
        *reinterpret_cast<uint2*>(g_yb + (size_t)r * DIM + idx * 4) = ub;
    }
    #pragma unroll
    for (int o = 16; o > 0; o >>= 1) s += __shfl_xor_sync(0xFFFFFFFFu, s, o);
    if (lane == 0) {
        g_diag[r] = s;
        g_rowsum[r] = 0.0f;
    }
    if (blockIdx.x == 0 && threadIdx.x == 0) out[0] = 0.0f;
}

// ---------------------------------------------------------------------------
// GEMM: banded occ=2 kernel. 128 threads (4 warps of 32 N-cols each);
// strip = 32 x-rows; exp-epilogue interleaved into the k-loop.
// DO NOT add code to this kernel — every fusion/addition attempt (R11, R12,
// R15) inflated the register allocation and regressed 20-40%.
// ---------------------------------------------------------------------------
__device__ __forceinline__ void load_B_panel(uint32_t Bb, int band, int tid) {
    const __nv_bfloat16* Bg = g_yb + (size_t)band * BANDC * DIM;
    #pragma unroll
    for (int it = 0; it < 32; it++) {
        int idx = tid + it * THREADS;      // 0..4095
        int r = idx >> 5, c = idx & 31;
        cp16(SWA(Bb, r, c), Bg + (size_t)r * DIM + c * 8);
    }
}
__device__ __forceinline__ void load_A_strip(uint32_t Ab, int srow, int tid) {
    const __nv_bfloat16* Ag = g_xb + (size_t)srow * SROWS * DIM;
    #pragma unroll
    for (int it = 0; it < 8; it++) {
        int idx = tid + it * THREADS;      // 0..1023
        int r = idx >> 5, c = idx & 31;
        cp16(SWA(Ab, r, c), Ag + (size_t)r * DIM + c * 8);
    }
}

// Compute strip into aN while doing the exp-epilogue of aO (rows row_old..+31).
__device__ __forceinline__ void strip_compute(
    uint32_t Ab, uint32_t Bb, int n_base,
    int a_row_off, int a_c_off, int b_row_off, int b_c_off,
    float (&aN)[2][4][4], float (&aO)[2][4][4],
    int row_old, int lid)
{
    #pragma unroll
    for (int i = 0; i < 2; i++)
        #pragma unroll
        for (int j = 0; j < 4; j++)
            #pragma unroll
            for (int r = 0; r < 4; r++) aN[i][j][r] = 0.0f;

    float lo[2] = {0.f, 0.f}, hi[2] = {0.f, 0.f};

    #pragma unroll
    for (int kk = 0; kk < 16; kk++) {
        uint32_t a[2][4];
        #pragma unroll
        for (int mi = 0; mi < 2; mi++) {
            int row = mi * 16 + a_row_off;
            int c = kk * 2 + a_c_off;
            LDSM4(a[mi][0], a[mi][1], a[mi][2], a[mi][3], SWA(Ab, row, c));
        }
        uint32_t b[2][4];
        #pragma unroll
        for (int p = 0; p < 2; p++) {
            int nrow = n_base + p * 16 + b_row_off;
            int c = kk * 2 + b_c_off;
            LDSM4(b[p][0], b[p][1], b[p][2], b[p][3], SWA(Bb, nrow, c));
        }
        // Interleave 2 elements of the previous strip's exp-epilogue.
        #pragma unroll
        for (int j = 0; j < 2; j++) {
            int e = kk * 2 + j;                    // 0..31
            int mi = e >> 4, ni = (e >> 2) & 3, r = e & 3;
            float v = ex2f(aO[mi][ni][r]);
            if (r < 2) lo[mi] += v; else hi[mi] += v;
        }
        #pragma unroll
        for (int mi = 0; mi < 2; mi++)
            #pragma unroll
            for (int ni = 0; ni < 4; ni++)
                MMA16816(aN[mi][ni], a[mi],
                         b[ni >> 1][(ni & 1) << 1],
                         b[ni >> 1][((ni & 1) << 1) + 1]);
    }

    // Finish previous strip: quad-shuffle row reduce + atomics.
    const int g = lid >> 2;
    #pragma unroll
    for (int mi = 0; mi < 2; mi++) {
        float l = lo[mi], h = hi[mi];
        l += __shfl_xor_sync(0xFFFFFFFFu, l, 1);
        l += __shfl_xor_sync(0xFFFFFFFFu, l, 2);
        h += __shfl_xor_sync(0xFFFFFFFFu, h, 1);
        h += __shfl_xor_sync(0xFFFFFFFFu, h, 2);
        if ((lid & 3) == 0) {
            atomicAdd(&g_rowsum[row_old + mi * 16 + g], l);
            atomicAdd(&g_rowsum[row_old + mi * 16 + g + 8], h);
        }
    }
}

// Epilogue-only flush for the final strip.
__device__ __forceinline__ void flush_acc(float (&aO)[2][4][4], int row_old, int lid) {
    const int g = lid >> 2;
    #pragma unroll
    for (int mi = 0; mi < 2; mi++) {
        float l = 0.f, h = 0.f;
        #pragma unroll
        for (int ni = 0; ni < 4; ni++) {
            l += ex2f(aO[mi][ni][0]) + ex2f(aO[mi][ni][1]);
            h += ex2f(aO[mi][ni][2]) + ex2f(aO[mi][ni][3]);
        }
        l += __shfl_xor_sync(0xFFFFFFFFu, l, 1);
        l += __shfl_xor_sync(0xFFFFFFFFu, l, 2);
        h += __shfl_xor_sync(0xFFFFFFFFu, h, 1);
        h += __shfl_xor_sync(0xFFFFFFFFu, h, 2);
        if ((lid & 3) == 0) {
            atomicAdd(&g_rowsum[row_old + mi * 16 + g], l);
            atomicAdd(&g_rowsum[row_old + mi * 16 + g + 8], h);
        }
    }
}

__global__ __launch_bounds__(THREADS, 2) void simsum_hmma_kernel() {
    extern __shared__ char smem[];
    const uint32_t sb = smem_to_u32(smem);
    const int tid = threadIdx.x;
    const int wid = tid >> 5, lid = tid & 31;
    const int n_base = wid * 32;               // warp grid 1 (M) x 4 (N)

    const int sub = lid >> 3, l7 = lid & 7;
    const int a_row_off = ((sub & 1) << 3) + l7;
    const int a_c_off   = sub >> 1;
    const int b_row_off = ((sub >> 1) << 3) + l7;
    const int b_c_off   = sub & 1;

    const int start = (int)(((long)blockIdx.x * TSTRIPS) / GRIDSZ);
    const int end   = (int)(((long)(blockIdx.x + 1) * TSTRIPS) / GRIDSZ);

    // Ping-pong accumulators; init so the first (fake) epilogue adds 0.
    float accA[2][4][4], accB[2][4][4];
    #pragma unroll
    for (int i = 0; i < 2; i++)
        #pragma unroll
        for (int j = 0; j < 4; j++)
            #pragma unroll
            for (int r = 0; r < 4; r++) { accA[i][j][r] = -1e30f; accB[i][j][r] = -1e30f; }

    int row_old = 0;
    int pcur = 0;
    for (int w = start; w < end; w++) {
        const int band = w >> 8, srow = w & (SPB - 1);
        if (srow == 0 || w == start) {
            CP_WAIT0();
            __syncthreads();                   // all warps done with old B panel
            load_B_panel(sb + SM_B, band, tid);
            load_A_strip(sb + SM_A(0), srow, tid);
            CP_COMMIT();
            CP_WAIT0();
            __syncthreads();
            pcur = 0;
        } else {
            CP_WAIT0();                        // prefetched A strip landed
            __syncthreads();
        }
        const bool pf = (w + 1 < end) && (((w + 1) & (SPB - 1)) != 0);
        if (pf) {
            load_A_strip(sb + SM_A(pcur ^ 1), srow + 1, tid);
            CP_COMMIT();
        }

        if ((w - start) & 1)
            strip_compute(sb + SM_A(pcur), sb + SM_B, n_base,
                          a_row_off, a_c_off, b_row_off, b_c_off,
                          accB, accA, row_old, lid);
        else
            strip_compute(sb + SM_A(pcur), sb + SM_B, n_base,
                          a_row_off, a_c_off, b_row_off, b_c_off,
                          accA, accB, row_old, lid);

        row_old = srow * SROWS;
        if (pf) pcur ^= 1;
    }

    if ((end - start) & 1) flush_acc(accA, row_old, lid);
    else                   flush_acc(accB, row_old, lid);
}

// ---------------------------------------------------------------------------
// Kernel: final loss — one row per thread, 32 blocks, atomic accumulate.
// ---------------------------------------------------------------------------
__global__ __launch_bounds__(256) void loss_kernel(float* __restrict__ out) {
    __shared__ float sh[256];
    int i = blockIdx.x * 256 + threadIdx.x;
    float d = g_diag[i] * INV_TEMP;
    float lneg = g_rowsum[i] - __expf(d);
    sh[threadIdx.x] = logf(lneg) - d;
    __syncthreads();
    #pragma unroll
    for (int o = 128; o > 0; o >>= 1) {
        if (threadIdx.x < o) sh[threadIdx.x] += sh[threadIdx.x + o];
        __syncthreads();
    }
    if (threadIdx.x == 0) atomicAdd(out, sh[0] * (1.0f / NROWS));
}

// ---------------------------------------------------------------------------
// Entry point
// ---------------------------------------------------------------------------
extern "C" void kernel_launch(void* const* d_in, const int* in_sizes, int n_in,
                              void* d_out, int out_size) {
    const float* X = (const float*)d_in[0];
    const float* Y = (const float*)d_in[1];
    float* out = (float*)d_out;

    static bool attr_set = false;
    if (!attr_set) {
        cudaFuncSetAttribute(simsum_hmma_kernel,
                             cudaFuncAttributeMaxDynamicSharedMemorySize, SMEM_TOTAL);
        attr_set = true;
    }

    prep_kernel<<<NROWS / 8, 256>>>(X, Y, out);
    simsum_hmma_kernel<<<GRIDSZ, THREADS, SMEM_TOTAL>>>();
    loss_kernel<<<NROWS / 256, 256>>>(out);
}